// round 4
// baseline (speedup 1.0000x reference)
#include <cuda_runtime.h>
#include <math.h>

#define N_NODES 50000
#define E_EDGES 800000
#define H 128
#define NR 16
#define CUTOFF 5.0f
#define LN_EPS 1e-5f
#define TE 64
#define EF_LD 280   // 275 padded to 280 (multiple of 8)
#define H_LD 130    // 128 padded
#define A_LD 260    // 256 padded (node kernel)

// Scatter accumulators (device globals: no allocation allowed)
__device__ float g_agg[N_NODES * H];
__device__ float g_cnt[N_NODES];
__device__ float g_delta[N_NODES * 3];

__device__ __forceinline__ float silu_f(float v) {
    return v / (1.0f + __expf(-v));
}

// ---------------------------------------------------------------------------
// Zero the accumulators (run before edge kernel each launch)
// ---------------------------------------------------------------------------
__global__ void zero_kernel() {
    const int total = N_NODES * H + N_NODES + N_NODES * 3;
    for (int i = blockIdx.x * blockDim.x + threadIdx.x; i < total;
         i += gridDim.x * blockDim.x) {
        if (i < N_NODES * H) g_agg[i] = 0.0f;
        else if (i < N_NODES * H + N_NODES) g_cnt[i - N_NODES * H] = 0.0f;
        else g_delta[i - N_NODES * H - N_NODES] = 0.0f;
    }
}

// ---------------------------------------------------------------------------
// Fused edge kernel: 64 edges per CTA, 256 threads.
// ef build -> GEMM1(K=275) -> silu -> LN -> GEMM2(K=128) -> silu ->
// GEMM3(K=128,N=64) -> silu -> dot Wc2 -> scatter (atomics)
// Thread mapping for GEMMs: ty = tid/16 owns rows ty*4..ty*4+3,
//                           tx = tid%16 owns cols tx*8..tx*8+7 (tx*4.. for GEMM3)
// ---------------------------------------------------------------------------
// smem float offsets
#define OFF_EF    0                   // [64][280]
#define OFF_H     (OFF_EF + TE*EF_LD)       // 17920, [64][130]
#define OFF_EH    (OFF_H + TE*H_LD)         // 26240, [64][130]
#define OFF_WB    (OFF_EH + TE*H_LD)        // 34560, [8][128]
#define OFF_BE1   (OFF_WB + 8*H)            // 35584
#define OFF_G1    (OFF_BE1 + H)
#define OFF_BT1   (OFF_G1 + H)
#define OFF_BE2   (OFF_BT1 + H)
#define OFF_BC1   (OFF_BE2 + H)             // 64
#define OFF_WC2   (OFF_BC1 + 64)            // 64
#define OFF_SRC   (OFF_WC2 + 64)            // 64 (int)
#define OFF_GATE  (OFF_SRC + 64)
#define OFF_COORD (OFF_GATE + 64)
#define OFF_UNIT  (OFF_COORD + 64)          // [64][3]
#define EDGE_SMEM_FLOATS (OFF_UNIT + 64*3)
#define EDGE_SMEM_BYTES  (EDGE_SMEM_FLOATS * 4)

__global__ __launch_bounds__(256) void edge_kernel(
    const float* __restrict__ x, const float* __restrict__ pos,
    const float* __restrict__ charge, const float* __restrict__ ea,
    const int* __restrict__ ei,
    const float* __restrict__ We1, const float* __restrict__ be1,
    const float* __restrict__ g1, const float* __restrict__ bt1,
    const float* __restrict__ We2, const float* __restrict__ be2,
    const float* __restrict__ Wc1, const float* __restrict__ bc1,
    const float* __restrict__ Wc2, const float* __restrict__ bc2)
{
    extern __shared__ float sm[];
    float* efS   = sm + OFF_EF;
    float* hS    = sm + OFF_H;
    float* ehS   = sm + OFF_EH;
    float* wb    = sm + OFF_WB;
    float* be1S  = sm + OFF_BE1;
    float* g1S   = sm + OFF_G1;
    float* bt1S  = sm + OFF_BT1;
    float* be2S  = sm + OFF_BE2;
    float* bc1S  = sm + OFF_BC1;
    float* wc2S  = sm + OFF_WC2;
    int*   srcS  = (int*)(sm + OFF_SRC);
    float* gateS = sm + OFF_GATE;
    float* coordS= sm + OFF_COORD;
    float* unitS = sm + OFF_UNIT;

    const int tid = threadIdx.x;
    const int tx = tid & 15;
    const int ty = tid >> 4;
    const int e0 = blockIdx.x * TE;

    // Stage small params
    if (tid < 128) {
        be1S[tid] = be1[tid]; g1S[tid] = g1[tid];
        bt1S[tid] = bt1[tid]; be2S[tid] = be2[tid];
    } else if (tid < 192) {
        int t = tid - 128;
        bc1S[t] = bc1[t]; wc2S[t] = Wc2[t];
    }

    // Per-edge geometry/meta features: threads 0..63 each own one edge
    if (tid < TE) {
        const int e = e0 + tid;
        const int s = ei[e];
        const int d = ei[E_EDGES + e];
        float rx = pos[d*3+0] - pos[s*3+0];
        float ry = pos[d*3+1] - pos[s*3+1];
        float rz = pos[d*3+2] - pos[s*3+2];
        float dist = sqrtf(rx*rx + ry*ry + rz*rz + 1e-8f);
        float invd = 1.0f / fmaxf(dist, 1e-6f);

        float4 eav = *(const float4*)(ea + e*4);
        // Legendre(|.| mean over degree 4) gates
        float ca = cosf(eav.x);
        float p2 = (3.0f*ca*ca - 1.0f) * 0.5f;
        float p3 = (5.0f*ca*p2 - 2.0f*ca) * (1.0f/3.0f);
        float ascore = 0.25f*(1.0f + fabsf(ca) + fabsf(p2) + fabsf(p3)) * eav.z;
        float cd = cosf(eav.y);
        float q2 = (3.0f*cd*cd - 1.0f) * 0.5f;
        float q3 = (5.0f*cd*q2 - 2.0f*cd) * (1.0f/3.0f);
        float dscore = 0.25f*(1.0f + fabsf(cd) + fabsf(q2) + fabsf(q3)) * eav.w;
        float gate = fminf(fmaxf(1.0f + 0.6f*(ascore + dscore), 0.35f), 2.5f);

        float clipped = fmaxf(dist, 1e-6f);
        float invc = 1.0f / clipped;
        float* mrow = efS + tid*EF_LD + 256;
        #pragma unroll
        for (int i = 0; i < NR; i++) {
            float fr = (float)(i+1) * (3.14159265358979323846f / CUTOFF);
            mrow[i] = sinf(fr * clipped) * invc * gate;
        }
        float qs = charge[s], qd = charge[d];
        mrow[16] = dist * (1.0f/CUTOFF) * gate;
        mrow[17] = qs * qd * gate;
        mrow[18] = fabsf(qs - qd) * gate;
        #pragma unroll
        for (int i = 19; i < 24; i++) mrow[i] = 0.0f;   // pad 275..279

        srcS[tid]  = s;
        gateS[tid] = gate;
        unitS[tid*3+0] = rx * invd;
        unitS[tid*3+1] = ry * invd;
        unitS[tid*3+2] = rz * invd;
    }

    // Gather x[src], x[dst] rows into efS (float4, reads served from L2)
    for (int i = tid; i < TE*32; i += 256) {
        const int r = i >> 5;
        const int c = (i & 31) << 2;
        const int e = e0 + r;
        const int s = ei[e];
        const int d = ei[E_EDGES + e];
        float4 vs = *(const float4*)(x + (size_t)s*H + c);
        float4 vd = *(const float4*)(x + (size_t)d*H + c);
        *(float4*)(efS + r*EF_LD + c)       = vs;
        *(float4*)(efS + r*EF_LD + 128 + c) = vd;
    }
    __syncthreads();

    // ---------------- GEMM1: h = ef @ We1  (K padded to 280) ----------------
    float acc[4][8];
    #pragma unroll
    for (int i = 0; i < 4; i++)
        #pragma unroll
        for (int j = 0; j < 8; j++) acc[i][j] = 0.0f;

    for (int kt = 0; kt < 35; kt++) {
        {
            const int row = tid >> 5;
            const int col = (tid & 31) << 2;
            const int gk = kt*8 + row;
            float4 v = (gk < 275) ? *(const float4*)(We1 + (size_t)gk*H + col)
                                  : make_float4(0.f, 0.f, 0.f, 0.f);
            *(float4*)(wb + row*H + col) = v;
        }
        __syncthreads();
        #pragma unroll
        for (int k = 0; k < 8; k++) {
            float b[8];
            *(float4*)(b)   = *(float4*)(wb + k*H + tx*8);
            *(float4*)(b+4) = *(float4*)(wb + k*H + tx*8 + 4);
            const int kk = kt*8 + k;
            #pragma unroll
            for (int i = 0; i < 4; i++) {
                float av = efS[(ty*4+i)*EF_LD + kk];
                #pragma unroll
                for (int j = 0; j < 8; j++) acc[i][j] = fmaf(av, b[j], acc[i][j]);
            }
        }
        __syncthreads();
    }

    // bias + silu + LayerNorm(g1, bt1) -> hS
    #pragma unroll
    for (int i = 0; i < 4; i++) {
        float v[8], s1 = 0.0f, s2 = 0.0f;
        #pragma unroll
        for (int j = 0; j < 8; j++) {
            float t = silu_f(acc[i][j] + be1S[tx*8+j]);
            v[j] = t; s1 += t; s2 += t*t;
        }
        #pragma unroll
        for (int m = 8; m >= 1; m >>= 1) {
            s1 += __shfl_xor_sync(0xffffffffu, s1, m);
            s2 += __shfl_xor_sync(0xffffffffu, s2, m);
        }
        float mean = s1 * (1.0f/128.0f);
        float var  = s2 * (1.0f/128.0f) - mean*mean;
        float rstd = rsqrtf(var + LN_EPS);
        const int r = ty*4 + i;
        #pragma unroll
        for (int j = 0; j < 8; j++) {
            const int c = tx*8 + j;
            hS[r*H_LD + c] = (v[j] - mean) * rstd * g1S[c] + bt1S[c];
        }
    }
    __syncthreads();

    // ---------------- GEMM2: eh = silu(h @ We2 + be2) ----------------
    #pragma unroll
    for (int i = 0; i < 4; i++)
        #pragma unroll
        for (int j = 0; j < 8; j++) acc[i][j] = 0.0f;

    for (int kt = 0; kt < 16; kt++) {
        {
            const int row = tid >> 5;
            const int col = (tid & 31) << 2;
            *(float4*)(wb + row*H + col) =
                *(const float4*)(We2 + (size_t)(kt*8 + row)*H + col);
        }
        __syncthreads();
        #pragma unroll
        for (int k = 0; k < 8; k++) {
            float b[8];
            *(float4*)(b)   = *(float4*)(wb + k*H + tx*8);
            *(float4*)(b+4) = *(float4*)(wb + k*H + tx*8 + 4);
            const int kk = kt*8 + k;
            #pragma unroll
            for (int i = 0; i < 4; i++) {
                float av = hS[(ty*4+i)*H_LD + kk];
                #pragma unroll
                for (int j = 0; j < 8; j++) acc[i][j] = fmaf(av, b[j], acc[i][j]);
            }
        }
        __syncthreads();
    }
    #pragma unroll
    for (int i = 0; i < 4; i++) {
        const int r = ty*4 + i;
        #pragma unroll
        for (int j = 0; j < 8; j++) {
            const int c = tx*8 + j;
            ehS[r*H_LD + c] = silu_f(acc[i][j] + be2S[c]);
        }
    }
    __syncthreads();

    // ---------------- GEMM3: c1 = eh @ Wc1 (N=64), coord = silu(c1)@Wc2+bc2 --
    float acc3[4][4];
    #pragma unroll
    for (int i = 0; i < 4; i++)
        #pragma unroll
        for (int j = 0; j < 4; j++) acc3[i][j] = 0.0f;

    for (int kt = 0; kt < 16; kt++) {
        {
            const int row = tid >> 5;
            const int col = (tid & 31) << 1;
            *(float2*)(wb + row*64 + col) =
                *(const float2*)(Wc1 + (size_t)(kt*8 + row)*64 + col);
        }
        __syncthreads();
        #pragma unroll
        for (int k = 0; k < 8; k++) {
            float b[4];
            *(float4*)(b) = *(float4*)(wb + k*64 + tx*4);
            const int kk = kt*8 + k;
            #pragma unroll
            for (int i = 0; i < 4; i++) {
                float av = ehS[(ty*4+i)*H_LD + kk];
                #pragma unroll
                for (int j = 0; j < 4; j++) acc3[i][j] = fmaf(av, b[j], acc3[i][j]);
            }
        }
        __syncthreads();
    }
    {
        const float bc2v = bc2[0];
        #pragma unroll
        for (int i = 0; i < 4; i++) {
            float p = 0.0f;
            #pragma unroll
            for (int j = 0; j < 4; j++) {
                const int c = tx*4 + j;
                p += silu_f(acc3[i][j] + bc1S[c]) * wc2S[c];
            }
            #pragma unroll
            for (int m = 8; m >= 1; m >>= 1)
                p += __shfl_xor_sync(0xffffffffu, p, m);
            if (tx == 0) coordS[ty*4 + i] = p + bc2v;
        }
    }
    __syncthreads();

    // ---------------- scatter (atomics; compile to RED) ----------------
    for (int i = tid; i < TE*H; i += 256) {
        const int r = i >> 7;
        const int c = i & 127;
        atomicAdd(&g_agg[(size_t)srcS[r]*H + c], ehS[r*H_LD + c]);
    }
    if (tid < TE) {
        const int s = srcS[tid];
        atomicAdd(&g_cnt[s], 1.0f);
        const float cg = coordS[tid] * gateS[tid];
        atomicAdd(&g_delta[s*3+0], unitS[tid*3+0] * cg);
        atomicAdd(&g_delta[s*3+1], unitS[tid*3+1] * cg);
        atomicAdd(&g_delta[s*3+2], unitS[tid*3+2] * cg);
    }
}

// ---------------------------------------------------------------------------
// Node kernel: x_new = x + LN(silu([x, agg/cnt] @ Wn + bn)); pos update.
// 64 nodes/CTA, 256 threads, K=256.
// ---------------------------------------------------------------------------
#define NOFF_A    0                         // [64][260]
#define NOFF_WB   (NOFF_A + TE*A_LD)        // [8][128]
#define NOFF_BN   (NOFF_WB + 8*H)
#define NOFF_GN   (NOFF_BN + H)
#define NOFF_BTN  (NOFF_GN + H)
#define NOFF_IC   (NOFF_BTN + H)            // 64
#define NODE_SMEM_FLOATS (NOFF_IC + 64)
#define NODE_SMEM_BYTES  (NODE_SMEM_FLOATS * 4)

__global__ __launch_bounds__(256) void node_kernel(
    const float* __restrict__ x, const float* __restrict__ pos,
    const float* __restrict__ Wn, const float* __restrict__ bn,
    const float* __restrict__ gn, const float* __restrict__ btn,
    float* __restrict__ out)
{
    extern __shared__ float sm[];
    float* aS   = sm + NOFF_A;
    float* wb   = sm + NOFF_WB;
    float* bnS  = sm + NOFF_BN;
    float* gnS  = sm + NOFF_GN;
    float* btnS = sm + NOFF_BTN;
    float* invcS= sm + NOFF_IC;

    const int tid = threadIdx.x;
    const int tx = tid & 15;
    const int ty = tid >> 4;
    const int n0 = blockIdx.x * TE;

    if (tid < 128) { bnS[tid] = bn[tid]; gnS[tid] = gn[tid]; btnS[tid] = btn[tid]; }
    if (tid < TE) {
        const int n = n0 + tid;
        float c = (n < N_NODES) ? fmaxf(g_cnt[n], 1.0f) : 1.0f;
        invcS[tid] = 1.0f / c;
    }
    __syncthreads();

    // Build A = [x_row, agg_row/cnt]
    for (int i = tid; i < TE*32; i += 256) {
        const int r = i >> 5;
        const int c4 = (i & 31) << 2;
        const int n = n0 + r;
        float4 vx = make_float4(0.f,0.f,0.f,0.f), va = vx;
        if (n < N_NODES) {
            vx = *(const float4*)(x + (size_t)n*H + c4);
            va = *(const float4*)(g_agg + (size_t)n*H + c4);
            float ic = invcS[r];
            va.x *= ic; va.y *= ic; va.z *= ic; va.w *= ic;
        }
        *(float4*)(aS + r*A_LD + c4)       = vx;
        *(float4*)(aS + r*A_LD + 128 + c4) = va;
    }
    __syncthreads();

    float acc[4][8];
    #pragma unroll
    for (int i = 0; i < 4; i++)
        #pragma unroll
        for (int j = 0; j < 8; j++) acc[i][j] = 0.0f;

    for (int kt = 0; kt < 32; kt++) {
        {
            const int row = tid >> 5;
            const int col = (tid & 31) << 2;
            *(float4*)(wb + row*H + col) =
                *(const float4*)(Wn + (size_t)(kt*8 + row)*H + col);
        }
        __syncthreads();
        #pragma unroll
        for (int k = 0; k < 8; k++) {
            float b[8];
            *(float4*)(b)   = *(float4*)(wb + k*H + tx*8);
            *(float4*)(b+4) = *(float4*)(wb + k*H + tx*8 + 4);
            const int kk = kt*8 + k;
            #pragma unroll
            for (int i = 0; i < 4; i++) {
                float av = aS[(ty*4+i)*A_LD + kk];
                #pragma unroll
                for (int j = 0; j < 8; j++) acc[i][j] = fmaf(av, b[j], acc[i][j]);
            }
        }
        __syncthreads();
    }

    // bias + silu + LN + residual write
    #pragma unroll
    for (int i = 0; i < 4; i++) {
        float v[8], s1 = 0.0f, s2 = 0.0f;
        #pragma unroll
        for (int j = 0; j < 8; j++) {
            float t = silu_f(acc[i][j] + bnS[tx*8+j]);
            v[j] = t; s1 += t; s2 += t*t;
        }
        #pragma unroll
        for (int m = 8; m >= 1; m >>= 1) {
            s1 += __shfl_xor_sync(0xffffffffu, s1, m);
            s2 += __shfl_xor_sync(0xffffffffu, s2, m);
        }
        float mean = s1 * (1.0f/128.0f);
        float var  = s2 * (1.0f/128.0f) - mean*mean;
        float rstd = rsqrtf(var + LN_EPS);
        const int r = ty*4 + i;
        const int n = n0 + r;
        if (n < N_NODES) {
            #pragma unroll
            for (int j = 0; j < 8; j++) {
                const int c = tx*8 + j;
                float ln = (v[j] - mean) * rstd * gnS[c] + btnS[c];
                out[(size_t)n*H + c] = x[(size_t)n*H + c] + ln;
            }
        }
    }

    // pos_new = pos + 0.1 * delta / cnt
    if (tid < TE) {
        const int n = n0 + tid;
        if (n < N_NODES) {
            const float ic = invcS[tid];
            float* outp = out + (size_t)N_NODES*H;
            #pragma unroll
            for (int k = 0; k < 3; k++)
                outp[n*3 + k] = pos[n*3 + k] + 0.1f * g_delta[n*3 + k] * ic;
        }
    }
}

// ---------------------------------------------------------------------------
extern "C" void kernel_launch(void* const* d_in, const int* in_sizes, int n_in,
                              void* d_out, int out_size)
{
    const float* x      = (const float*)d_in[0];
    const float* pos    = (const float*)d_in[1];
    const float* charge = (const float*)d_in[2];
    const float* ea     = (const float*)d_in[3];
    const int*   ei     = (const int*)d_in[4];
    const float* We1    = (const float*)d_in[5];
    const float* be1    = (const float*)d_in[6];
    const float* g1     = (const float*)d_in[7];
    const float* bt1    = (const float*)d_in[8];
    const float* We2    = (const float*)d_in[9];
    const float* be2    = (const float*)d_in[10];
    const float* Wn     = (const float*)d_in[11];
    const float* bn     = (const float*)d_in[12];
    const float* gn     = (const float*)d_in[13];
    const float* btn    = (const float*)d_in[14];
    const float* Wc1    = (const float*)d_in[15];
    const float* bc1    = (const float*)d_in[16];
    const float* Wc2    = (const float*)d_in[17];
    const float* bc2    = (const float*)d_in[18];
    float* out = (float*)d_out;

    cudaFuncSetAttribute(edge_kernel, cudaFuncAttributeMaxDynamicSharedMemorySize,
                         EDGE_SMEM_BYTES);
    cudaFuncSetAttribute(node_kernel, cudaFuncAttributeMaxDynamicSharedMemorySize,
                         NODE_SMEM_BYTES);

    zero_kernel<<<256, 256>>>();
    edge_kernel<<<E_EDGES / TE, 256, EDGE_SMEM_BYTES>>>(
        x, pos, charge, ea, ei, We1, be1, g1, bt1, We2, be2, Wc1, bc1, Wc2, bc2);
    node_kernel<<<(N_NODES + TE - 1) / TE, 256, NODE_SMEM_BYTES>>>(
        x, pos, Wn, bn, gn, btn, out);
}

// round 8
// speedup vs baseline: 3.1522x; 3.1522x over previous
#include <cuda_runtime.h>
#include <math.h>
#include <stdint.h>

#define N_NODES 50000
#define E_EDGES 800000
#define H 128
#define NR 16
#define CUTOFF 5.0f
#define LN_EPS 1e-5f

#define MT 128
#define THREADS 256
#define TE 64
#define A_LD 260   // node kernel A stride

// ---- edge kernel SMEM layout (float offsets) ----
#define AF     0          // A tile: 128 x 292 (ef -> h -> eh in cols 0..127)
#define ALD    292
#define F_B0   37376      // weight chunk buf0: [32][136]
#define F_B1   41728      // buf1
#define BLD    136
#define BLD3   72         // GEMM3 chunk stride ([32][72])
#define F_LN1  46080      // LN partial s1 [128][2]
#define F_LN2  46336      // LN partial s2 [128][2]
#define F_CP   46592      // coord partials [128][2]
#define F_SRC  46848      // 128 int
#define F_GATE 46976
#define F_UNIT 47104      // 128*3
#define F_BE1  47488
#define F_G1   47616
#define F_BT1  47744
#define F_BE2  47872
#define F_BC1  48000
#define F_WC2  48064
#define SM_FLOATS 48128
#define SM_BYTES  (SM_FLOATS * 4)

__device__ float g_agg[N_NODES * H];
__device__ float g_cnt[N_NODES];
__device__ float g_delta[N_NODES * 3];

__device__ __forceinline__ float silu_f(float v) { return v / (1.0f + __expf(-v)); }
__device__ __forceinline__ uint32_t f2tf(float f) {
    uint32_t u; asm("cvt.rna.tf32.f32 %0, %1;" : "=r"(u) : "f"(f)); return u;
}
// m16n8k8 tf32 MMA. Fragment map (PTX ISA): g=lane>>2, t=lane&3
//  a0=A[g][t]   a1=A[g+8][t]   a2=A[g][t+4]   a3=A[g+8][t+4]
//  b0=B[k=t][n=g]  b1=B[k=t+4][n=g]
//  c0=C[g][2t] c1=C[g][2t+1] c2=C[g+8][2t] c3=C[g+8][2t+1]
__device__ __forceinline__ void mma8(float* c, const uint32_t* a,
                                     uint32_t b0, uint32_t b1) {
    asm volatile(
        "mma.sync.aligned.m16n8k8.row.col.f32.tf32.tf32.f32 "
        "{%0,%1,%2,%3},{%4,%5,%6,%7},{%8,%9},{%0,%1,%2,%3};"
        : "+f"(c[0]), "+f"(c[1]), "+f"(c[2]), "+f"(c[3])
        : "r"(a[0]), "r"(a[1]), "r"(a[2]), "r"(a[3]), "r"(b0), "r"(b1));
}
__device__ __forceinline__ void red2(float* p, float a, float b) {
    asm volatile("red.global.add.v2.f32 [%0], {%1,%2};" :: "l"(p), "f"(a), "f"(b)
                 : "memory");
}

__global__ void zero_kernel() {
    const int total = N_NODES * H + N_NODES + N_NODES * 3;
    for (int i = blockIdx.x * blockDim.x + threadIdx.x; i < total;
         i += gridDim.x * blockDim.x) {
        if (i < N_NODES * H) g_agg[i] = 0.0f;
        else if (i < N_NODES * H + N_NODES) g_cnt[i - N_NODES * H] = 0.0f;
        else g_delta[i - N_NODES * H - N_NODES] = 0.0f;
    }
}

// stage a [32 x 128] f32 chunk of W (row-major [K][128]) -> regs -> smem tf32
__device__ __forceinline__ void ldg128(float4* st, const float* __restrict__ W,
                                       int kt, int kmax) {
    #pragma unroll
    for (int i = 0; i < 4; i++) {
        int task = threadIdx.x + i * 256;
        int kl = task >> 5, n4 = (task & 31) << 2;
        int gk = kt * 32 + kl;
        st[i] = (gk < kmax) ? *(const float4*)(W + (size_t)gk * 128 + n4)
                            : make_float4(0.f, 0.f, 0.f, 0.f);
    }
}
__device__ __forceinline__ void sts128(const float4* st, uint32_t* B) {
    #pragma unroll
    for (int i = 0; i < 4; i++) {
        int task = threadIdx.x + i * 256;
        int kl = task >> 5, n4 = (task & 31) << 2;
        uint4 u;
        u.x = f2tf(st[i].x); u.y = f2tf(st[i].y);
        u.z = f2tf(st[i].z); u.w = f2tf(st[i].w);
        *(uint4*)(B + kl * BLD + n4) = u;
    }
}
// [32 x 64] chunk of Wc1 (row-major [128][64])
__device__ __forceinline__ void ldg64(float4* st, const float* __restrict__ W, int kt) {
    #pragma unroll
    for (int i = 0; i < 2; i++) {
        int task = threadIdx.x + i * 256;
        int kl = task >> 4, n4 = (task & 15) << 2;
        st[i] = *(const float4*)(W + (size_t)(kt * 32 + kl) * 64 + n4);
    }
}
__device__ __forceinline__ void sts64(const float4* st, uint32_t* B) {
    #pragma unroll
    for (int i = 0; i < 2; i++) {
        int task = threadIdx.x + i * 256;
        int kl = task >> 4, n4 = (task & 15) << 2;
        uint4 u;
        u.x = f2tf(st[i].x); u.y = f2tf(st[i].y);
        u.z = f2tf(st[i].z); u.w = f2tf(st[i].w);
        *(uint4*)(B + kl * BLD3 + n4) = u;
    }
}

__global__ __launch_bounds__(THREADS, 1) void edge_mma_kernel(
    const float* __restrict__ x, const float* __restrict__ pos,
    const float* __restrict__ charge, const float* __restrict__ ea,
    const int* __restrict__ ei,
    const float* __restrict__ We1, const float* __restrict__ be1,
    const float* __restrict__ g1, const float* __restrict__ bt1,
    const float* __restrict__ We2, const float* __restrict__ be2,
    const float* __restrict__ Wc1, const float* __restrict__ bc1,
    const float* __restrict__ Wc2, const float* __restrict__ bc2)
{
    extern __shared__ float sm[];
    uint32_t* Au = (uint32_t*)(sm + AF);
    int* srcS = (int*)(sm + F_SRC);

    const int tid = threadIdx.x;
    const int w = tid >> 5, lane = tid & 31;
    const int g = lane >> 2, t = lane & 3;
    const int mb = (w & 3) * 32;      // warp M strip (32 rows)
    const int ns = w >> 2;            // warp N strip (0/1)
    const int e0 = blockIdx.x * MT;

    // small params
    if (tid < 128) {
        sm[F_BE1 + tid] = be1[tid]; sm[F_G1 + tid] = g1[tid];
        sm[F_BT1 + tid] = bt1[tid]; sm[F_BE2 + tid] = be2[tid];
    } else if (tid < 192) {
        int q = tid - 128;
        sm[F_BC1 + q] = bc1[q]; sm[F_WC2 + q] = Wc2[q];
    }

    // per-edge geometry + feature cols 256..287
    if (tid < MT) {
        const int e = e0 + tid;
        const int s = ei[e], d = ei[E_EDGES + e];
        float rx = pos[d*3+0] - pos[s*3+0];
        float ry = pos[d*3+1] - pos[s*3+1];
        float rz = pos[d*3+2] - pos[s*3+2];
        float dist = sqrtf(rx*rx + ry*ry + rz*rz + 1e-8f);
        float invd = 1.0f / fmaxf(dist, 1e-6f);
        float4 eav = *(const float4*)(ea + e*4);
        float ca = cosf(eav.x);
        float p2 = (3.0f*ca*ca - 1.0f) * 0.5f;
        float p3 = (5.0f*ca*p2 - 2.0f*ca) * (1.0f/3.0f);
        float ascore = 0.25f*(1.0f + fabsf(ca) + fabsf(p2) + fabsf(p3)) * eav.z;
        float cd = cosf(eav.y);
        float q2 = (3.0f*cd*cd - 1.0f) * 0.5f;
        float q3 = (5.0f*cd*q2 - 2.0f*cd) * (1.0f/3.0f);
        float dscore = 0.25f*(1.0f + fabsf(cd) + fabsf(q2) + fabsf(q3)) * eav.w;
        float gate = fminf(fmaxf(1.0f + 0.6f*(ascore + dscore), 0.35f), 2.5f);
        float clipped = fmaxf(dist, 1e-6f);
        float invc = 1.0f / clipped;
        float feat[32];
        #pragma unroll
        for (int i = 0; i < NR; i++) {
            float fr = (float)(i+1) * (3.14159265358979323846f / CUTOFF);
            feat[i] = sinf(fr * clipped) * invc * gate;
        }
        float qs = charge[s], qd = charge[d];
        feat[16] = dist * (1.0f/CUTOFF) * gate;
        feat[17] = qs * qd * gate;
        feat[18] = fabsf(qs - qd) * gate;
        #pragma unroll
        for (int i = 19; i < 32; i++) feat[i] = 0.0f;
        #pragma unroll
        for (int j = 0; j < 8; j++) {
            uint4 u;
            u.x = f2tf(feat[4*j+0]); u.y = f2tf(feat[4*j+1]);
            u.z = f2tf(feat[4*j+2]); u.w = f2tf(feat[4*j+3]);
            *(uint4*)&Au[tid*ALD + 256 + 4*j] = u;
        }
        srcS[tid] = s;
        sm[F_GATE + tid] = gate;
        sm[F_UNIT + tid*3+0] = rx*invd;
        sm[F_UNIT + tid*3+1] = ry*invd;
        sm[F_UNIT + tid*3+2] = rz*invd;
    }

    // gather x[src], x[dst] -> A cols 0..255 (tf32)
    for (int i = tid; i < MT*32; i += THREADS) {
        const int r = i >> 5, c4 = (i & 31) << 2;
        const int e = e0 + r;
        const int s = ei[e], d = ei[E_EDGES + e];
        float4 vs = *(const float4*)(x + (size_t)s*H + c4);
        float4 vd = *(const float4*)(x + (size_t)d*H + c4);
        uint4 us, ud;
        us.x = f2tf(vs.x); us.y = f2tf(vs.y); us.z = f2tf(vs.z); us.w = f2tf(vs.w);
        ud.x = f2tf(vd.x); ud.y = f2tf(vd.y); ud.z = f2tf(vd.z); ud.w = f2tf(vd.w);
        *(uint4*)&Au[r*ALD + c4]       = us;
        *(uint4*)&Au[r*ALD + 128 + c4] = ud;
    }

    // preload GEMM1 chunk 0
    float4 stg[4];
    ldg128(stg, We1, 0, 275);
    sts128(stg, (uint32_t*)(sm + F_B0));
    __syncthreads();

    float acc[2][8][4];
    #pragma unroll
    for (int mi = 0; mi < 2; mi++)
        #pragma unroll
        for (int nt = 0; nt < 8; nt++)
            #pragma unroll
            for (int c = 0; c < 4; c++) acc[mi][nt][c] = 0.0f;

    // ============== GEMM1: A(128x288) @ We1 -> 128x128 ==============
    for (int kt = 0; kt < 9; kt++) {
        const bool have = (kt + 1) < 9;
        if (have) ldg128(stg, We1, kt + 1, 275);
        const uint32_t* Bs = (const uint32_t*)(sm + ((kt & 1) ? F_B1 : F_B0));
        #pragma unroll
        for (int ks = 0; ks < 4; ks++) {
            const int ka = kt*32 + ks*8 + t;
            uint32_t a[2][4];
            #pragma unroll
            for (int mi = 0; mi < 2; mi++) {
                const int r0 = (mb + mi*16 + g) * ALD;
                a[mi][0] = Au[r0 + ka];
                a[mi][1] = Au[r0 + 8*ALD + ka];
                a[mi][2] = Au[r0 + ka + 4];
                a[mi][3] = Au[r0 + 8*ALD + ka + 4];
            }
            const int kb = (ks*8 + t) * BLD;
            #pragma unroll
            for (int nt = 0; nt < 8; nt++) {
                const int n = ns*64 + nt*8 + g;
                uint32_t b0 = Bs[kb + n], b1 = Bs[kb + 4*BLD + n];
                mma8(acc[0][nt], a[0], b0, b1);
                mma8(acc[1][nt], a[1], b0, b1);
            }
        }
        if (have) sts128(stg, (uint32_t*)(sm + ((kt & 1) ? F_B0 : F_B1)));
        __syncthreads();
    }

    // ===== Epi1: h = LN(silu(D+be1)) -> A cols 0..127; preload We2 chunk0 =====
    {
        ldg128(stg, We2, 0, 128);
        float s1[2][2] = {{0,0},{0,0}}, s2[2][2] = {{0,0},{0,0}};
        #pragma unroll
        for (int mi = 0; mi < 2; mi++)
            #pragma unroll
            for (int nt = 0; nt < 8; nt++)
                #pragma unroll
                for (int c = 0; c < 4; c++) {
                    const int col = ns*64 + nt*8 + 2*t + (c & 1);
                    float v = silu_f(acc[mi][nt][c] + sm[F_BE1 + col]);
                    acc[mi][nt][c] = v;
                    s1[mi][c >> 1] += v; s2[mi][c >> 1] += v * v;
                }
        #pragma unroll
        for (int mi = 0; mi < 2; mi++)
            #pragma unroll
            for (int hh = 0; hh < 2; hh++) {
                float a1 = s1[mi][hh], a2 = s2[mi][hh];
                a1 += __shfl_xor_sync(0xffffffffu, a1, 1);
                a1 += __shfl_xor_sync(0xffffffffu, a1, 2);
                a2 += __shfl_xor_sync(0xffffffffu, a2, 1);
                a2 += __shfl_xor_sync(0xffffffffu, a2, 2);
                if (t == 0) {
                    const int row = mb + mi*16 + hh*8 + g;
                    sm[F_LN1 + row*2 + ns] = a1;
                    sm[F_LN2 + row*2 + ns] = a2;
                }
            }
        __syncthreads();
        #pragma unroll
        for (int mi = 0; mi < 2; mi++)
            #pragma unroll
            for (int hh = 0; hh < 2; hh++) {
                const int row = mb + mi*16 + hh*8 + g;
                float m  = (sm[F_LN1 + row*2] + sm[F_LN1 + row*2 + 1]) * (1.f/128.f);
                float vv = (sm[F_LN2 + row*2] + sm[F_LN2 + row*2 + 1]) * (1.f/128.f) - m*m;
                float rstd = rsqrtf(vv + LN_EPS);
                #pragma unroll
                for (int nt = 0; nt < 8; nt++) {
                    const int col = ns*64 + nt*8 + 2*t;
                    float v0 = (acc[mi][nt][hh*2]   - m) * rstd * sm[F_G1+col]   + sm[F_BT1+col];
                    float v1 = (acc[mi][nt][hh*2+1] - m) * rstd * sm[F_G1+col+1] + sm[F_BT1+col+1];
                    uint2 u; u.x = f2tf(v0); u.y = f2tf(v1);
                    *(uint2*)&Au[row*ALD + col] = u;
                }
            }
        sts128(stg, (uint32_t*)(sm + F_B0));
        __syncthreads();
    }

    // ============== GEMM2: h @ We2 -> 128x128 ==============
    #pragma unroll
    for (int mi = 0; mi < 2; mi++)
        #pragma unroll
        for (int nt = 0; nt < 8; nt++)
            #pragma unroll
            for (int c = 0; c < 4; c++) acc[mi][nt][c] = 0.0f;

    for (int kt = 0; kt < 4; kt++) {
        const bool have = (kt + 1) < 4;
        if (have) ldg128(stg, We2, kt + 1, 128);
        const uint32_t* Bs = (const uint32_t*)(sm + ((kt & 1) ? F_B1 : F_B0));
        #pragma unroll
        for (int ks = 0; ks < 4; ks++) {
            const int ka = kt*32 + ks*8 + t;
            uint32_t a[2][4];
            #pragma unroll
            for (int mi = 0; mi < 2; mi++) {
                const int r0 = (mb + mi*16 + g) * ALD;
                a[mi][0] = Au[r0 + ka];
                a[mi][1] = Au[r0 + 8*ALD + ka];
                a[mi][2] = Au[r0 + ka + 4];
                a[mi][3] = Au[r0 + 8*ALD + ka + 4];
            }
            const int kb = (ks*8 + t) * BLD;
            #pragma unroll
            for (int nt = 0; nt < 8; nt++) {
                const int n = ns*64 + nt*8 + g;
                uint32_t b0 = Bs[kb + n], b1 = Bs[kb + 4*BLD + n];
                mma8(acc[0][nt], a[0], b0, b1);
                mma8(acc[1][nt], a[1], b0, b1);
            }
        }
        if (have) sts128(stg, (uint32_t*)(sm + ((kt & 1) ? F_B0 : F_B1)));
        __syncthreads();
    }

    // ===== Epi2: eh = silu(D+be2) -> red to g_agg + A cols 0..127; Wc1 chunk0 =====
    float4 stg3[2];
    {
        ldg64(stg3, Wc1, 0);
        #pragma unroll
        for (int mi = 0; mi < 2; mi++)
            #pragma unroll
            for (int hh = 0; hh < 2; hh++) {
                const int row = mb + mi*16 + hh*8 + g;
                const int sr = srcS[row];
                float* base = g_agg + (size_t)sr * H;
                #pragma unroll
                for (int nt = 0; nt < 8; nt++) {
                    const int col = ns*64 + nt*8 + 2*t;
                    float v0 = silu_f(acc[mi][nt][hh*2]   + sm[F_BE2+col]);
                    float v1 = silu_f(acc[mi][nt][hh*2+1] + sm[F_BE2+col+1]);
                    red2(base + col, v0, v1);
                    uint2 u; u.x = f2tf(v0); u.y = f2tf(v1);
                    *(uint2*)&Au[row*ALD + col] = u;
                }
            }
        if (tid < 128) atomicAdd(&g_cnt[srcS[tid]], 1.0f);
        sts64(stg3, (uint32_t*)(sm + F_B0));
        __syncthreads();
    }

    // ============== GEMM3: eh @ Wc1 -> 128x64 ==============
    float acc3[2][4][4];
    #pragma unroll
    for (int mi = 0; mi < 2; mi++)
        #pragma unroll
        for (int nt = 0; nt < 4; nt++)
            #pragma unroll
            for (int c = 0; c < 4; c++) acc3[mi][nt][c] = 0.0f;

    for (int kt = 0; kt < 4; kt++) {
        const bool have = (kt + 1) < 4;
        if (have) ldg64(stg3, Wc1, kt + 1);
        const uint32_t* Bs = (const uint32_t*)(sm + ((kt & 1) ? F_B1 : F_B0));
        #pragma unroll
        for (int ks = 0; ks < 4; ks++) {
            const int ka = kt*32 + ks*8 + t;
            uint32_t a[2][4];
            #pragma unroll
            for (int mi = 0; mi < 2; mi++) {
                const int r0 = (mb + mi*16 + g) * ALD;
                a[mi][0] = Au[r0 + ka];
                a[mi][1] = Au[r0 + 8*ALD + ka];
                a[mi][2] = Au[r0 + ka + 4];
                a[mi][3] = Au[r0 + 8*ALD + ka + 4];
            }
            const int kb = (ks*8 + t) * BLD3;
            #pragma unroll
            for (int nt = 0; nt < 4; nt++) {
                const int n = ns*32 + nt*8 + g;
                uint32_t b0 = Bs[kb + n], b1 = Bs[kb + 4*BLD3 + n];
                mma8(acc3[0][nt], a[0], b0, b1);
                mma8(acc3[1][nt], a[1], b0, b1);
            }
        }
        if (have) sts64(stg3, (uint32_t*)(sm + ((kt & 1) ? F_B0 : F_B1)));
        __syncthreads();
    }

    // ===== Epi3: coord = silu(D+bc1)@Wc2 + bc2; scatter delta =====
    #pragma unroll
    for (int mi = 0; mi < 2; mi++)
        #pragma unroll
        for (int hh = 0; hh < 2; hh++) {
            float p = 0.0f;
            #pragma unroll
            for (int nt = 0; nt < 4; nt++)
                #pragma unroll
                for (int j = 0; j < 2; j++) {
                    const int col = ns*32 + nt*8 + 2*t + j;
                    p += silu_f(acc3[mi][nt][hh*2+j] + sm[F_BC1+col]) * sm[F_WC2+col];
                }
            p += __shfl_xor_sync(0xffffffffu, p, 1);
            p += __shfl_xor_sync(0xffffffffu, p, 2);
            if (t == 0) {
                const int row = mb + mi*16 + hh*8 + g;
                sm[F_CP + row*2 + ns] = p;
            }
        }
    __syncthreads();
    if (tid < 128) {
        const float coord = sm[F_CP + tid*2] + sm[F_CP + tid*2 + 1] + bc2[0];
        const float cg = coord * sm[F_GATE + tid];
        const int s = srcS[tid];
        atomicAdd(&g_delta[s*3+0], sm[F_UNIT + tid*3+0] * cg);
        atomicAdd(&g_delta[s*3+1], sm[F_UNIT + tid*3+1] * cg);
        atomicAdd(&g_delta[s*3+2], sm[F_UNIT + tid*3+2] * cg);
    }
}

// ---------------------------------------------------------------------------
// Node kernel (FFMA): x_new = x + LN(silu([x, agg/cnt]@Wn+bn)); pos update
// ---------------------------------------------------------------------------
#define NOFF_A    0
#define NOFF_WB   (NOFF_A + TE*A_LD)
#define NOFF_BN   (NOFF_WB + 8*H)
#define NOFF_GN   (NOFF_BN + H)
#define NOFF_BTN  (NOFF_GN + H)
#define NOFF_IC   (NOFF_BTN + H)
#define NODE_SMEM_BYTES  ((NOFF_IC + 64) * 4)

__global__ __launch_bounds__(256) void node_kernel(
    const float* __restrict__ x, const float* __restrict__ pos,
    const float* __restrict__ Wn, const float* __restrict__ bn,
    const float* __restrict__ gn, const float* __restrict__ btn,
    float* __restrict__ out)
{
    extern __shared__ float sm[];
    float* aS = sm + NOFF_A;
    float* wb = sm + NOFF_WB;
    float* bnS = sm + NOFF_BN;
    float* gnS = sm + NOFF_GN;
    float* btnS = sm + NOFF_BTN;
    float* invcS = sm + NOFF_IC;
    const int tid = threadIdx.x, tx = tid & 15, ty = tid >> 4;
    const int n0 = blockIdx.x * TE;

    if (tid < 128) { bnS[tid] = bn[tid]; gnS[tid] = gn[tid]; btnS[tid] = btn[tid]; }
    if (tid < TE) {
        const int n = n0 + tid;
        invcS[tid] = 1.0f / ((n < N_NODES) ? fmaxf(g_cnt[n], 1.0f) : 1.0f);
    }
    __syncthreads();

    for (int i = tid; i < TE*32; i += 256) {
        const int r = i >> 5, c4 = (i & 31) << 2;
        const int n = n0 + r;
        float4 vx = make_float4(0.f,0.f,0.f,0.f), va = vx;
        if (n < N_NODES) {
            vx = *(const float4*)(x + (size_t)n*H + c4);
            va = *(const float4*)(g_agg + (size_t)n*H + c4);
            float ic = invcS[r];
            va.x *= ic; va.y *= ic; va.z *= ic; va.w *= ic;
        }
        *(float4*)(aS + r*A_LD + c4)       = vx;
        *(float4*)(aS + r*A_LD + 128 + c4) = va;
    }
    __syncthreads();

    float acc[4][8];
    #pragma unroll
    for (int i = 0; i < 4; i++)
        #pragma unroll
        for (int j = 0; j < 8; j++) acc[i][j] = 0.0f;

    for (int kt = 0; kt < 32; kt++) {
        {
            const int row = tid >> 5, col = (tid & 31) << 2;
            *(float4*)(wb + row*H + col) =
                *(const float4*)(Wn + (size_t)(kt*8 + row)*H + col);
        }
        __syncthreads();
        #pragma unroll
        for (int k = 0; k < 8; k++) {
            float b[8];
            *(float4*)(b)   = *(float4*)(wb + k*H + tx*8);
            *(float4*)(b+4) = *(float4*)(wb + k*H + tx*8 + 4);
            const int kk = kt*8 + k;
            #pragma unroll
            for (int i = 0; i < 4; i++) {
                float av = aS[(ty*4+i)*A_LD + kk];
                #pragma unroll
                for (int j = 0; j < 8; j++) acc[i][j] = fmaf(av, b[j], acc[i][j]);
            }
        }
        __syncthreads();
    }

    #pragma unroll
    for (int i = 0; i < 4; i++) {
        float v[8], s1 = 0.0f, s2 = 0.0f;
        #pragma unroll
        for (int j = 0; j < 8; j++) {
            float tt = silu_f(acc[i][j] + bnS[tx*8+j]);
            v[j] = tt; s1 += tt; s2 += tt*tt;
        }
        #pragma unroll
        for (int m = 8; m >= 1; m >>= 1) {
            s1 += __shfl_xor_sync(0xffffffffu, s1, m);
            s2 += __shfl_xor_sync(0xffffffffu, s2, m);
        }
        float mean = s1 * (1.0f/128.0f);
        float var  = s2 * (1.0f/128.0f) - mean*mean;
        float rstd = rsqrtf(var + LN_EPS);
        const int n = n0 + ty*4 + i;
        if (n < N_NODES) {
            #pragma unroll
            for (int j = 0; j < 8; j++) {
                const int c = tx*8 + j;
                out[(size_t)n*H + c] = x[(size_t)n*H + c]
                    + (v[j] - mean) * rstd * gnS[c] + btnS[c];
            }
        }
    }
    if (tid < TE) {
        const int n = n0 + tid;
        if (n < N_NODES) {
            const float ic = invcS[tid];
            float* outp = out + (size_t)N_NODES*H;
            #pragma unroll
            for (int k = 0; k < 3; k++)
                outp[n*3 + k] = pos[n*3 + k] + 0.1f * g_delta[n*3 + k] * ic;
        }
    }
}

extern "C" void kernel_launch(void* const* d_in, const int* in_sizes, int n_in,
                              void* d_out, int out_size)
{
    const float* x      = (const float*)d_in[0];
    const float* pos    = (const float*)d_in[1];
    const float* charge = (const float*)d_in[2];
    const float* ea     = (const float*)d_in[3];
    const int*   ei     = (const int*)d_in[4];
    const float* We1    = (const float*)d_in[5];
    const float* be1    = (const float*)d_in[6];
    const float* g1     = (const float*)d_in[7];
    const float* bt1    = (const float*)d_in[8];
    const float* We2    = (const float*)d_in[9];
    const float* be2    = (const float*)d_in[10];
    const float* Wn     = (const float*)d_in[11];
    const float* bn     = (const float*)d_in[12];
    const float* gn     = (const float*)d_in[13];
    const float* btn    = (const float*)d_in[14];
    const float* Wc1    = (const float*)d_in[15];
    const float* bc1    = (const float*)d_in[16];
    const float* Wc2    = (const float*)d_in[17];
    const float* bc2    = (const float*)d_in[18];
    float* out = (float*)d_out;

    cudaFuncSetAttribute(edge_mma_kernel, cudaFuncAttributeMaxDynamicSharedMemorySize,
                         SM_BYTES);
    cudaFuncSetAttribute(node_kernel, cudaFuncAttributeMaxDynamicSharedMemorySize,
                         NODE_SMEM_BYTES);

    zero_kernel<<<256, 256>>>();
    edge_mma_kernel<<<E_EDGES / MT, THREADS, SM_BYTES>>>(
        x, pos, charge, ea, ei, We1, be1, g1, bt1, We2, be2, Wc1, bc1, Wc2, bc2);
    node_kernel<<<(N_NODES + TE - 1) / TE, 256, NODE_SMEM_BYTES>>>(
        x, pos, Wn, bn, gn, btn, out);
}